// round 11
// baseline (speedup 1.0000x reference)
#include <cuda_runtime.h>
#include <cstdint>

#define BB   32
#define NN   4096
#define CIN  128
#define COUT 128
#define MM   256
#define SPLITK_A 4

__device__ __forceinline__ float tf32r(float f) {
    uint32_t u;
    asm("cvt.rna.tf32.f32 %0, %1;" : "=r"(u) : "f"(f));
    return __uint_as_float(u);
}
__device__ __forceinline__ uint32_t tf32r_u(uint32_t v) {
    uint32_t r;
    asm("cvt.rna.tf32.f32 %0, %1;" : "=r"(r) : "f"(__uint_as_float(v)));
    return r;
}
__device__ __forceinline__ uint32_t smem_to_u32(const void* p) {
    uint32_t a;
    asm("{ .reg .u64 t; cvta.to.shared.u64 t, %1; cvt.u32.u64 %0, t; }" : "=r"(a) : "l"(p));
    return a;
}

// ===========================================================================
// Scratch (device globals — allocation-guard safe)
// ===========================================================================
__device__ __align__(16) float g_Ur[NN * MM];                          // tf32-rounded U [n][m]
__device__ __align__(16) float g_xsp[BB * SPLITK_A * MM * CIN];        // stage-A split-K partials
__device__ __align__(16) float g_wt[MM * CIN * COUT];                  // [m][c][o], tf32-rounded
__device__ __align__(16) float g_ospec[BB * MM * COUT];                // [b][m][o] tf32-rounded

// ===========================================================================
// kRound: U -> tf32(RN)
// ===========================================================================
__global__ __launch_bounds__(256) void kRound(const float* __restrict__ src,
                                              float* __restrict__ dst, int n4) {
    for (int i = blockIdx.x * blockDim.x + threadIdx.x; i < n4; i += gridDim.x * blockDim.x) {
        float4 v = ((const float4*)src)[i];
        v.x = tf32r(v.x); v.y = tf32r(v.y); v.z = tf32r(v.z); v.w = tf32r(v.w);
        ((float4*)dst)[i] = v;
    }
}

// ===========================================================================
// kT: W_real[c][o][m] -> g_wt[m][c][o], tf32-rounded (stage B is now tf32 MMA)
// ===========================================================================
__global__ __launch_bounds__(256) void kT(const float* __restrict__ W) {
    __shared__ float tile[32][33];
    const int c = blockIdx.x, o0 = blockIdx.y * 32, m0 = blockIdx.z * 32;
    const int tx = threadIdx.x, ty = threadIdx.y;
#pragma unroll
    for (int j = 0; j < 32; j += 8)
        tile[ty + j][tx] = W[((size_t)c * COUT + (o0 + ty + j)) * MM + m0 + tx];
    __syncthreads();
#pragma unroll
    for (int j = 0; j < 32; j += 8)
        g_wt[((size_t)(m0 + ty + j) * CIN + c) * COUT + o0 + tx] = tf32r(tile[tx][ty + j]);
}

// ===========================================================================
// tf32 GEMM: CTA 128x128, 4 warps of 64x64, BK=32, 3-stage cp.async pipeline.
// ===========================================================================
template <bool ATRANS, bool CVTB, int KCTA, int SPLITK>
__global__ __launch_bounds__(128, 2) void kGemm(
    const float* __restrict__ gA, const float* __restrict__ gB, float* __restrict__ gC,
    int lda, int ldb, int ldc, size_t strideB, size_t strideC)
{
    constexpr int ASZ = ATRANS ? 32 * 136 : 128 * 36;
    constexpr int BSZ = 32 * 136;
    constexpr int BUFST = ASZ + BSZ;
    extern __shared__ float sm[];
    const uint32_t smU = smem_to_u32(sm);

    const int tid = threadIdx.x;
    const int w = tid >> 5, lane = tid & 31;
    const int m_w = (w & 1) * 64, j_w = (w >> 1) * 64;
    const int r4 = lane >> 2, c4 = lane & 3;

    const int i0 = blockIdx.x * 128;
    const int z  = blockIdx.z;
    const int b  = z / SPLITK;
    const int kbase = (z - b * SPLITK) * KCTA;
    const float* gBb = gB + (size_t)b * strideB;

    float acc[4][8][4];
#pragma unroll
    for (int mt = 0; mt < 4; mt++)
#pragma unroll
        for (int nt = 0; nt < 8; nt++)
#pragma unroll
            for (int q = 0; q < 4; q++) acc[mt][nt][q] = 0.f;

    auto load = [&](int k0, int buf) {
        uint32_t aU = smU + (uint32_t)(buf * BUFST) * 4u;
        uint32_t bU = aU + (uint32_t)ASZ * 4u;
#pragma unroll
        for (int it = 0; it < 8; it++) {
            int t4 = tid + it * 128;
            const float* src; uint32_t so;
            if (ATRANS) {
                int kr = t4 >> 5, cc = (t4 & 31) * 4;
                src = gA + (size_t)(k0 + kr) * lda + i0 + cc;
                so = (uint32_t)(kr * 136 + cc);
            } else {
                int rr = t4 >> 3, cc = (t4 & 7) * 4;
                src = gA + (size_t)(i0 + rr) * lda + k0 + cc;
                so = (uint32_t)(rr * 36 + cc);
            }
            asm volatile("cp.async.cg.shared.global [%0], [%1], 16;" :: "r"(aU + so * 4u), "l"(src));
        }
#pragma unroll
        for (int it = 0; it < 8; it++) {
            int t4 = tid + it * 128;
            int kr = t4 >> 5, cc = (t4 & 31) * 4;
            const float* src = gBb + (size_t)(k0 + kr) * ldb + cc;
            asm volatile("cp.async.cg.shared.global [%0], [%1], 16;"
                         :: "r"(bU + (uint32_t)(kr * 136 + cc) * 4u), "l"(src));
        }
        asm volatile("cp.async.commit_group;");
    };

    constexpr int NCH = KCTA / 32;
    load(kbase, 0);
    if (NCH > 1) load(kbase + 32, 1);

    int buf = 0;
    for (int ch = 0; ch < NCH; ch++) {
        if (ch + 2 < NCH) {
            int nb = buf + 2; if (nb >= 3) nb -= 3;
            load(kbase + (ch + 2) * 32, nb);
            asm volatile("cp.async.wait_group 2;");
        } else if (ch + 1 < NCH) {
            asm volatile("cp.async.wait_group 1;");
        } else {
            asm volatile("cp.async.wait_group 0;");
        }
        __syncthreads();

        const float* as = sm + buf * BUFST;
        const float* bs = as + ASZ;
#pragma unroll
        for (int kk = 0; kk < 32; kk += 8) {
            uint32_t a[4][4], bf[8][2];
#pragma unroll
            for (int mt = 0; mt < 4; mt++) {
                const int ib = m_w + mt * 16 + r4;
                if (ATRANS) {
                    const float* p0 = as + (kk + c4) * 136 + ib;
                    a[mt][0] = __float_as_uint(p0[0]);
                    a[mt][1] = __float_as_uint(p0[8]);
                    a[mt][2] = __float_as_uint(p0[4 * 136]);
                    a[mt][3] = __float_as_uint(p0[4 * 136 + 8]);
                } else {
                    const float* p0 = as + ib * 36 + kk + c4;
                    a[mt][0] = __float_as_uint(p0[0]);
                    a[mt][1] = __float_as_uint(p0[8 * 36]);
                    a[mt][2] = __float_as_uint(p0[4]);
                    a[mt][3] = __float_as_uint(p0[8 * 36 + 4]);
                }
            }
#pragma unroll
            for (int nt = 0; nt < 8; nt++) {
                const float* pb = bs + (kk + c4) * 136 + j_w + nt * 8 + r4;
                uint32_t b0 = __float_as_uint(pb[0]);
                uint32_t b1 = __float_as_uint(pb[4 * 136]);
                if (CVTB) { b0 = tf32r_u(b0); b1 = tf32r_u(b1); }
                bf[nt][0] = b0; bf[nt][1] = b1;
            }
#pragma unroll
            for (int mt = 0; mt < 4; mt++)
#pragma unroll
                for (int nt = 0; nt < 8; nt++)
                    asm volatile(
                        "mma.sync.aligned.m16n8k8.row.col.f32.tf32.tf32.f32 "
                        "{%0,%1,%2,%3}, {%4,%5,%6,%7}, {%8,%9}, {%0,%1,%2,%3};"
                        : "+f"(acc[mt][nt][0]), "+f"(acc[mt][nt][1]),
                          "+f"(acc[mt][nt][2]), "+f"(acc[mt][nt][3])
                        : "r"(a[mt][0]), "r"(a[mt][1]), "r"(a[mt][2]), "r"(a[mt][3]),
                          "r"(bf[nt][0]), "r"(bf[nt][1]));
        }
        __syncthreads();
        if (++buf >= 3) buf = 0;
    }

    float* cb = gC + (size_t)z * strideC;
#pragma unroll
    for (int mt = 0; mt < 4; mt++)
#pragma unroll
        for (int nt = 0; nt < 8; nt++) {
            const int r = i0 + m_w + mt * 16 + r4;
            const int c = j_w + nt * 8 + c4 * 2;
            float2 v0 = { acc[mt][nt][0], acc[mt][nt][1] };
            float2 v1 = { acc[mt][nt][2], acc[mt][nt][3] };
            *(float2*)&cb[(size_t)r * ldc + c] = v0;
            *(float2*)&cb[(size_t)(r + 8) * ldc + c] = v1;
        }
}

// ===========================================================================
// Stage B v3 (tensor): ospec[b][m][o] = sum_c xsum[b][c] * wt[m][c][o]
//   xsum = fold of split-K partials, stored tf32 in smem [c][b] (pad 40).
//   W chunk [128c][64o] cp.async'd whole (pad 72), tf32 pre-rounded by kT.
//   Grid (m, o-half) = 512 CTAs, 256 threads = 8 warps: 2(b) x 4(o) layout,
//   each warp 16b x 16o: 1 m-frag x 2 n-frags x 16 k-steps = 32 MMAs.
// ===========================================================================
#define B3_XPAD 40
#define B3_WPAD 72
#define B3_XSZ (CIN * B3_XPAD)                  // 5120 floats
#define SMEM_B3 ((B3_XSZ + CIN * B3_WPAD) * 4)  // 57344 B

__global__ __launch_bounds__(256) void kB3() {
    extern __shared__ float smB[];
    float* xsT = smB;                 // [c][b] pad 40
    float* Ws  = smB + B3_XSZ;        // [c][o] pad 72
    const uint32_t wsU = smem_to_u32(Ws);

    const int m = blockIdx.x;
    const int h = blockIdx.y;
    const int t = threadIdx.x;
    const int w = t >> 5, lane = t & 31;
    const int r4 = lane >> 2, c4 = lane & 3;
    const int m_w = (w & 1) * 16;       // b-offset of warp
    const int j_w = (w >> 1) * 16;      // o-offset of warp

    // --- cp.async the whole W[m] half: 128 rows x 64 floats (one group) ---
    const float* wtm = g_wt + (size_t)m * CIN * COUT + h * 64;
#pragma unroll
    for (int it = 0; it < 8; it++) {
        int t4 = t + it * 256;          // 0..2047
        int cr = t4 >> 4;               // 0..127
        int oc = (t4 & 15) * 4;         // 0..60
        asm volatile("cp.async.cg.shared.global [%0], [%1], 16;"
                     :: "r"(wsU + (uint32_t)((cr * B3_WPAD + oc) * 4)),
                        "l"(wtm + (size_t)cr * COUT + oc));
    }
    asm volatile("cp.async.commit_group;");

    // --- fold split-K partials -> xsT[c][b], tf32-rounded (overlaps W load) ---
    for (int it = 0; it < 4; it++) {
        int wk = t + it * 256;          // 0..1023 (float4 units)
        int b = wk >> 5;                // 0..31
        int cg = (wk & 31) * 4;         // 0..124
        const float* base = g_xsp + (((size_t)b * SPLITK_A) * MM + m) * CIN + cg;
        float4 v = *(const float4*)base;
#pragma unroll
        for (int s = 1; s < SPLITK_A; s++) {
            float4 p = *(const float4*)(base + (size_t)s * MM * CIN);
            v.x += p.x; v.y += p.y; v.z += p.z; v.w += p.w;
        }
        xsT[(cg + 0) * B3_XPAD + b] = tf32r(v.x);
        xsT[(cg + 1) * B3_XPAD + b] = tf32r(v.y);
        xsT[(cg + 2) * B3_XPAD + b] = tf32r(v.z);
        xsT[(cg + 3) * B3_XPAD + b] = tf32r(v.w);
    }

    asm volatile("cp.async.wait_group 0;");
    __syncthreads();

    float acc[2][4];
#pragma unroll
    for (int nt = 0; nt < 2; nt++)
#pragma unroll
        for (int q = 0; q < 4; q++) acc[nt][q] = 0.f;

#pragma unroll
    for (int kk = 0; kk < CIN; kk += 8) {
        const float* pa = xsT + (kk + c4) * B3_XPAD + m_w + r4;
        uint32_t a0 = __float_as_uint(pa[0]);
        uint32_t a1 = __float_as_uint(pa[8]);
        uint32_t a2 = __float_as_uint(pa[4 * B3_XPAD]);
        uint32_t a3 = __float_as_uint(pa[4 * B3_XPAD + 8]);
#pragma unroll
        for (int nt = 0; nt < 2; nt++) {
            const float* pb = Ws + (kk + c4) * B3_WPAD + j_w + nt * 8 + r4;
            uint32_t b0 = __float_as_uint(pb[0]);
            uint32_t b1 = __float_as_uint(pb[4 * B3_WPAD]);
            asm volatile(
                "mma.sync.aligned.m16n8k8.row.col.f32.tf32.tf32.f32 "
                "{%0,%1,%2,%3}, {%4,%5,%6,%7}, {%8,%9}, {%0,%1,%2,%3};"
                : "+f"(acc[nt][0]), "+f"(acc[nt][1]), "+f"(acc[nt][2]), "+f"(acc[nt][3])
                : "r"(a0), "r"(a1), "r"(a2), "r"(a3), "r"(b0), "r"(b1));
        }
    }

    // --- epilogue: ospec[b][m][o], tf32-rounded for stage C ---
#pragma unroll
    for (int nt = 0; nt < 2; nt++) {
        const int o = h * 64 + j_w + nt * 8 + c4 * 2;
        const int b0r = m_w + r4;
        float2 v0 = { tf32r(acc[nt][0]), tf32r(acc[nt][1]) };
        float2 v1 = { tf32r(acc[nt][2]), tf32r(acc[nt][3]) };
        *(float2*)&g_ospec[((size_t)b0r * MM + m) * COUT + o] = v0;
        *(float2*)&g_ospec[((size_t)(b0r + 8) * MM + m) * COUT + o] = v1;
    }
}

// ===========================================================================
// Launch
// ===========================================================================
static constexpr int SMEM_GA = 3 * (32 * 136 + 32 * 136) * 4;    // 104448 B
static constexpr int SMEM_GC = 3 * (128 * 36 + 32 * 136) * 4;    // 107520 B

extern "C" void kernel_launch(void* const* d_in, const int* in_sizes, int n_in,
                              void* d_out, int out_size) {
    const float* x = (const float*)d_in[0];   // [32,4096,128]
    const float* U = (const float*)d_in[1];   // [4096,256]
    const float* W = (const float*)d_in[2];   // [128,128,256] (W_imag d_in[3] is dead)
    float* out = (float*)d_out;               // [32,4096,128]

    float* dUr;  cudaGetSymbolAddress((void**)&dUr,  g_Ur);
    float* dxsp; cudaGetSymbolAddress((void**)&dxsp, g_xsp);
    float* dos;  cudaGetSymbolAddress((void**)&dos,  g_ospec);

    cudaFuncSetAttribute((const void*)kGemm<true,  true,  NN / SPLITK_A, SPLITK_A>,
                         cudaFuncAttributeMaxDynamicSharedMemorySize, SMEM_GA);
    cudaFuncSetAttribute((const void*)kGemm<false, false, MM, 1>,
                         cudaFuncAttributeMaxDynamicSharedMemorySize, SMEM_GC);
    cudaFuncSetAttribute((const void*)kB3,
                         cudaFuncAttributeMaxDynamicSharedMemorySize, SMEM_B3);

    // Prep: round U once (x is rounded in-register inside stage A)
    kRound<<<256, 256>>>(U, dUr, NN * MM / 4);
    kT<<<dim3(CIN, COUT / 32, MM / 32), dim3(32, 8)>>>(W);

    // Stage A: xsp[b][s][m][c] partials = sum_{n slice} U[n][m] * x[b][n][c]
    kGemm<true, true, NN / SPLITK_A, SPLITK_A>
        <<<dim3(MM / 128, 1, BB * SPLITK_A), 128, SMEM_GA>>>(
            dUr, x, dxsp, MM, CIN, CIN, (size_t)NN * CIN, (size_t)MM * CIN);

    // Stage B: fold partials + per-mode channel mix on tensor pipe
    kB3<<<dim3(MM, 2), 256, SMEM_B3>>>();

    // Stage C: out[b][n][o] = sum_m U[n][m] * ospec[b][m][o]
    kGemm<false, false, MM, 1>
        <<<dim3(NN / 128, 1, BB), 128, SMEM_GC>>>(
            dUr, dos, out, MM, COUT, COUT, (size_t)MM * COUT, (size_t)NN * COUT);
}

// round 12
// speedup vs baseline: 1.0405x; 1.0405x over previous
#include <cuda_runtime.h>
#include <cstdint>

#define BB   32
#define NN   4096
#define CIN  128
#define COUT 128
#define MM   256
#define SPLITK_A 4

__device__ __forceinline__ float tf32r(float f) {
    uint32_t u;
    asm("cvt.rna.tf32.f32 %0, %1;" : "=r"(u) : "f"(f));
    return __uint_as_float(u);
}
__device__ __forceinline__ uint32_t tf32r_u(uint32_t v) {
    uint32_t r;
    asm("cvt.rna.tf32.f32 %0, %1;" : "=r"(r) : "f"(__uint_as_float(v)));
    return r;
}
__device__ __forceinline__ uint32_t smem_to_u32(const void* p) {
    uint32_t a;
    asm("{ .reg .u64 t; cvta.to.shared.u64 t, %1; cvt.u32.u64 %0, t; }" : "=r"(a) : "l"(p));
    return a;
}

// ===========================================================================
// Scratch (device globals — allocation-guard safe)
// ===========================================================================
__device__ __align__(16) float g_Ur[NN * MM];                          // tf32-rounded U [n][m]
__device__ __align__(16) float g_xsp[BB * SPLITK_A * MM * CIN];        // stage-A split-K partials
__device__ __align__(16) float g_xsum[MM * CIN * BB];                  // folded, [m][c][b], tf32
__device__ __align__(16) float g_wt[MM * CIN * COUT];                  // [m][c][o], tf32-rounded
__device__ __align__(16) float g_ospec[BB * MM * COUT];                // [b][m][o] tf32-rounded

// ===========================================================================
// kRound: U -> tf32(RN)
// ===========================================================================
__global__ __launch_bounds__(256) void kRound(const float* __restrict__ src,
                                              float* __restrict__ dst, int n4) {
    for (int i = blockIdx.x * blockDim.x + threadIdx.x; i < n4; i += gridDim.x * blockDim.x) {
        float4 v = ((const float4*)src)[i];
        v.x = tf32r(v.x); v.y = tf32r(v.y); v.z = tf32r(v.z); v.w = tf32r(v.w);
        ((float4*)dst)[i] = v;
    }
}

// ===========================================================================
// kT: W_real[c][o][m] -> g_wt[m][c][o], tf32-rounded
// ===========================================================================
__global__ __launch_bounds__(256) void kT(const float* __restrict__ W) {
    __shared__ float tile[32][33];
    const int c = blockIdx.x, o0 = blockIdx.y * 32, m0 = blockIdx.z * 32;
    const int tx = threadIdx.x, ty = threadIdx.y;
#pragma unroll
    for (int j = 0; j < 32; j += 8)
        tile[ty + j][tx] = W[((size_t)c * COUT + (o0 + ty + j)) * MM + m0 + tx];
    __syncthreads();
#pragma unroll
    for (int j = 0; j < 32; j += 8)
        g_wt[((size_t)(m0 + ty + j) * CIN + c) * COUT + o0 + tx] = tf32r(tile[tx][ty + j]);
}

// ===========================================================================
// tf32 GEMM (R8 config): CTA 128x128, 4 warps of 64x64, BK=32, double-buffered.
// ===========================================================================
template <bool ATRANS, bool CVTB, int KCTA, int SPLITK>
__global__ __launch_bounds__(128, 2) void kGemm(
    const float* __restrict__ gA, const float* __restrict__ gB, float* __restrict__ gC,
    int lda, int ldb, int ldc, size_t strideB, size_t strideC)
{
    constexpr int ASZ = ATRANS ? 32 * 136 : 128 * 36;
    constexpr int BSZ = 32 * 136;
    constexpr int BUFST = ASZ + BSZ;
    extern __shared__ float sm[];
    const uint32_t smU = smem_to_u32(sm);

    const int tid = threadIdx.x;
    const int w = tid >> 5, lane = tid & 31;
    const int m_w = (w & 1) * 64, j_w = (w >> 1) * 64;
    const int r4 = lane >> 2, c4 = lane & 3;

    const int i0 = blockIdx.x * 128;
    const int z  = blockIdx.z;
    const int b  = z / SPLITK;
    const int kbase = (z - b * SPLITK) * KCTA;
    const float* gBb = gB + (size_t)b * strideB;

    float acc[4][8][4];
#pragma unroll
    for (int mt = 0; mt < 4; mt++)
#pragma unroll
        for (int nt = 0; nt < 8; nt++)
#pragma unroll
            for (int q = 0; q < 4; q++) acc[mt][nt][q] = 0.f;

    auto load = [&](int k0, int buf) {
        uint32_t aU = smU + (uint32_t)(buf * BUFST) * 4u;
        uint32_t bU = aU + (uint32_t)ASZ * 4u;
#pragma unroll
        for (int it = 0; it < 8; it++) {
            int t4 = tid + it * 128;
            const float* src; uint32_t so;
            if (ATRANS) {
                int kr = t4 >> 5, cc = (t4 & 31) * 4;
                src = gA + (size_t)(k0 + kr) * lda + i0 + cc;
                so = (uint32_t)(kr * 136 + cc);
            } else {
                int rr = t4 >> 3, cc = (t4 & 7) * 4;
                src = gA + (size_t)(i0 + rr) * lda + k0 + cc;
                so = (uint32_t)(rr * 36 + cc);
            }
            asm volatile("cp.async.cg.shared.global [%0], [%1], 16;" :: "r"(aU + so * 4u), "l"(src));
        }
#pragma unroll
        for (int it = 0; it < 8; it++) {
            int t4 = tid + it * 128;
            int kr = t4 >> 5, cc = (t4 & 31) * 4;
            const float* src = gBb + (size_t)(k0 + kr) * ldb + cc;
            asm volatile("cp.async.cg.shared.global [%0], [%1], 16;"
                         :: "r"(bU + (uint32_t)(kr * 136 + cc) * 4u), "l"(src));
        }
        asm volatile("cp.async.commit_group;");
    };

    load(kbase, 0);
    constexpr int NCH = KCTA / 32;
    for (int ch = 0; ch < NCH; ch++) {
        const int buf = ch & 1;
        if (ch + 1 < NCH) {
            load(kbase + (ch + 1) * 32, buf ^ 1);
            asm volatile("cp.async.wait_group 1;");
        } else {
            asm volatile("cp.async.wait_group 0;");
        }
        __syncthreads();

        const float* as = sm + buf * BUFST;
        const float* bs = as + ASZ;
#pragma unroll
        for (int kk = 0; kk < 32; kk += 8) {
            uint32_t a[4][4], bf[8][2];
#pragma unroll
            for (int mt = 0; mt < 4; mt++) {
                const int ib = m_w + mt * 16 + r4;
                if (ATRANS) {
                    const float* p0 = as + (kk + c4) * 136 + ib;
                    a[mt][0] = __float_as_uint(p0[0]);
                    a[mt][1] = __float_as_uint(p0[8]);
                    a[mt][2] = __float_as_uint(p0[4 * 136]);
                    a[mt][3] = __float_as_uint(p0[4 * 136 + 8]);
                } else {
                    const float* p0 = as + ib * 36 + kk + c4;
                    a[mt][0] = __float_as_uint(p0[0]);
                    a[mt][1] = __float_as_uint(p0[8 * 36]);
                    a[mt][2] = __float_as_uint(p0[4]);
                    a[mt][3] = __float_as_uint(p0[8 * 36 + 4]);
                }
            }
#pragma unroll
            for (int nt = 0; nt < 8; nt++) {
                const float* pb = bs + (kk + c4) * 136 + j_w + nt * 8 + r4;
                uint32_t b0 = __float_as_uint(pb[0]);
                uint32_t b1 = __float_as_uint(pb[4 * 136]);
                if (CVTB) { b0 = tf32r_u(b0); b1 = tf32r_u(b1); }
                bf[nt][0] = b0; bf[nt][1] = b1;
            }
#pragma unroll
            for (int mt = 0; mt < 4; mt++)
#pragma unroll
                for (int nt = 0; nt < 8; nt++)
                    asm volatile(
                        "mma.sync.aligned.m16n8k8.row.col.f32.tf32.tf32.f32 "
                        "{%0,%1,%2,%3}, {%4,%5,%6,%7}, {%8,%9}, {%0,%1,%2,%3};"
                        : "+f"(acc[mt][nt][0]), "+f"(acc[mt][nt][1]),
                          "+f"(acc[mt][nt][2]), "+f"(acc[mt][nt][3])
                        : "r"(a[mt][0]), "r"(a[mt][1]), "r"(a[mt][2]), "r"(a[mt][3]),
                          "r"(bf[nt][0]), "r"(bf[nt][1]));
        }
        __syncthreads();
    }

    float* cb = gC + (size_t)z * strideC;
#pragma unroll
    for (int mt = 0; mt < 4; mt++)
#pragma unroll
        for (int nt = 0; nt < 8; nt++) {
            const int r = i0 + m_w + mt * 16 + r4;
            const int c = j_w + nt * 8 + c4 * 2;
            float2 v0 = { acc[mt][nt][0], acc[mt][nt][1] };
            float2 v1 = { acc[mt][nt][2], acc[mt][nt][3] };
            *(float2*)&cb[(size_t)r * ldc + c] = v0;
            *(float2*)&cb[(size_t)(r + 8) * ldc + c] = v1;
        }
}

// ===========================================================================
// kFold: fold split-K partials once: g_xsum[m][c][b] = tf32(sum_s xsp[b][s][m][c])
// Grid (MM, CIN/32), block (32, 8). Coalesced read (c) and write (b) via
// 32x32 smem transpose.
// ===========================================================================
__global__ __launch_bounds__(256) void kFold() {
    __shared__ float tile[32][33];     // [b][c]
    const int m  = blockIdx.x;
    const int c0 = blockIdx.y * 32;
    const int tx = threadIdx.x, ty = threadIdx.y;

#pragma unroll
    for (int j = 0; j < 32; j += 8) {
        const int b = ty + j;
        const float* base = g_xsp + (((size_t)b * SPLITK_A) * MM + m) * CIN + c0 + tx;
        float v = base[0];
#pragma unroll
        for (int s = 1; s < SPLITK_A; s++) v += base[(size_t)s * MM * CIN];
        tile[b][tx] = v;
    }
    __syncthreads();
#pragma unroll
    for (int j = 0; j < 32; j += 8)
        g_xsum[((size_t)m * CIN + c0 + ty + j) * BB + tx] = tf32r(tile[tx][ty + j]);
}

// ===========================================================================
// Stage B v4 (tensor): ospec[b][m][o] = sum_c xsum[m][c][b] * wt[m][c][o]
//   Both operands cp.async'd in ONE group (xsum slice 16 KB + W half 32 KB);
//   no synchronous loads anywhere before the MMA loop.
//   Grid (m, o-half) = 512 CTAs, 8 warps: 2(b) x 4(o), 16x16 per warp.
// ===========================================================================
#define B3_XPAD 40
#define B3_WPAD 72
#define B3_XSZ (CIN * B3_XPAD)                  // 5120 floats
#define SMEM_B3 ((B3_XSZ + CIN * B3_WPAD) * 4)  // 57344 B

__global__ __launch_bounds__(256) void kB3() {
    extern __shared__ float smB[];
    float* xsT = smB;                 // [c][b] pad 40
    float* Ws  = smB + B3_XSZ;        // [c][o] pad 72
    const uint32_t xsU = smem_to_u32(xsT);
    const uint32_t wsU = smem_to_u32(Ws);

    const int m = blockIdx.x;
    const int h = blockIdx.y;
    const int t = threadIdx.x;
    const int w = t >> 5, lane = t & 31;
    const int r4 = lane >> 2, c4 = lane & 3;
    const int m_w = (w & 1) * 16;       // b-offset of warp
    const int j_w = (w >> 1) * 16;      // o-offset of warp

    // --- cp.async xsum slice: 128 c-rows x 32 b floats (128B rows) ---
    const float* xm = g_xsum + (size_t)m * CIN * BB;
#pragma unroll
    for (int it = 0; it < 4; it++) {
        int t4 = t + it * 256;          // 0..1023 (16B chunks)
        int cr = t4 >> 3;               // 0..127
        int bc = (t4 & 7) * 4;          // 0..28
        asm volatile("cp.async.cg.shared.global [%0], [%1], 16;"
                     :: "r"(xsU + (uint32_t)((cr * B3_XPAD + bc) * 4)),
                        "l"(xm + (size_t)cr * BB + bc));
    }
    // --- cp.async W half: 128 c-rows x 64 o floats ---
    const float* wtm = g_wt + (size_t)m * CIN * COUT + h * 64;
#pragma unroll
    for (int it = 0; it < 8; it++) {
        int t4 = t + it * 256;          // 0..2047
        int cr = t4 >> 4;               // 0..127
        int oc = (t4 & 15) * 4;         // 0..60
        asm volatile("cp.async.cg.shared.global [%0], [%1], 16;"
                     :: "r"(wsU + (uint32_t)((cr * B3_WPAD + oc) * 4)),
                        "l"(wtm + (size_t)cr * COUT + oc));
    }
    asm volatile("cp.async.commit_group;");
    asm volatile("cp.async.wait_group 0;");
    __syncthreads();

    float acc[2][4];
#pragma unroll
    for (int nt = 0; nt < 2; nt++)
#pragma unroll
        for (int q = 0; q < 4; q++) acc[nt][q] = 0.f;

#pragma unroll
    for (int kk = 0; kk < CIN; kk += 8) {
        const float* pa = xsT + (kk + c4) * B3_XPAD + m_w + r4;
        uint32_t a0 = __float_as_uint(pa[0]);
        uint32_t a1 = __float_as_uint(pa[8]);
        uint32_t a2 = __float_as_uint(pa[4 * B3_XPAD]);
        uint32_t a3 = __float_as_uint(pa[4 * B3_XPAD + 8]);
#pragma unroll
        for (int nt = 0; nt < 2; nt++) {
            const float* pb = Ws + (kk + c4) * B3_WPAD + j_w + nt * 8 + r4;
            uint32_t b0 = __float_as_uint(pb[0]);
            uint32_t b1 = __float_as_uint(pb[4 * B3_WPAD]);
            asm volatile(
                "mma.sync.aligned.m16n8k8.row.col.f32.tf32.tf32.f32 "
                "{%0,%1,%2,%3}, {%4,%5,%6,%7}, {%8,%9}, {%0,%1,%2,%3};"
                : "+f"(acc[nt][0]), "+f"(acc[nt][1]), "+f"(acc[nt][2]), "+f"(acc[nt][3])
                : "r"(a0), "r"(a1), "r"(a2), "r"(a3), "r"(b0), "r"(b1));
        }
    }

    // --- epilogue: ospec[b][m][o], tf32-rounded for stage C ---
#pragma unroll
    for (int nt = 0; nt < 2; nt++) {
        const int o = h * 64 + j_w + nt * 8 + c4 * 2;
        const int b0r = m_w + r4;
        float2 v0 = { tf32r(acc[nt][0]), tf32r(acc[nt][1]) };
        float2 v1 = { tf32r(acc[nt][2]), tf32r(acc[nt][3]) };
        *(float2*)&g_ospec[((size_t)b0r * MM + m) * COUT + o] = v0;
        *(float2*)&g_ospec[((size_t)(b0r + 8) * MM + m) * COUT + o] = v1;
    }
}

// ===========================================================================
// Launch
// ===========================================================================
static constexpr int SMEM_GA = 2 * (32 * 136 + 32 * 136) * 4;    // 69632 B
static constexpr int SMEM_GC = 2 * (128 * 36 + 32 * 136) * 4;    // 71680 B

extern "C" void kernel_launch(void* const* d_in, const int* in_sizes, int n_in,
                              void* d_out, int out_size) {
    const float* x = (const float*)d_in[0];   // [32,4096,128]
    const float* U = (const float*)d_in[1];   // [4096,256]
    const float* W = (const float*)d_in[2];   // [128,128,256] (W_imag d_in[3] is dead)
    float* out = (float*)d_out;               // [32,4096,128]

    float* dUr;  cudaGetSymbolAddress((void**)&dUr,  g_Ur);
    float* dxsp; cudaGetSymbolAddress((void**)&dxsp, g_xsp);
    float* dos;  cudaGetSymbolAddress((void**)&dos,  g_ospec);

    cudaFuncSetAttribute((const void*)kGemm<true,  true,  NN / SPLITK_A, SPLITK_A>,
                         cudaFuncAttributeMaxDynamicSharedMemorySize, SMEM_GA);
    cudaFuncSetAttribute((const void*)kGemm<false, false, MM, 1>,
                         cudaFuncAttributeMaxDynamicSharedMemorySize, SMEM_GC);
    cudaFuncSetAttribute((const void*)kB3,
                         cudaFuncAttributeMaxDynamicSharedMemorySize, SMEM_B3);

    // Prep: round U once (x is rounded in-register inside stage A)
    kRound<<<256, 256>>>(U, dUr, NN * MM / 4);
    kT<<<dim3(CIN, COUT / 32, MM / 32), dim3(32, 8)>>>(W);

    // Stage A: xsp[b][s][m][c] partials = sum_{n slice} U[n][m] * x[b][n][c]
    kGemm<true, true, NN / SPLITK_A, SPLITK_A>
        <<<dim3(MM / 128, 1, BB * SPLITK_A), 128, SMEM_GA>>>(
            dUr, x, dxsp, MM, CIN, CIN, (size_t)NN * CIN, (size_t)MM * CIN);

    // Fold split-K partials once (transposed for kB3's A operand)
    kFold<<<dim3(MM, CIN / 32), dim3(32, 8)>>>();

    // Stage B: per-mode channel mix on tensor pipe (fully async operands)
    kB3<<<dim3(MM, 2), 256, SMEM_B3>>>();

    // Stage C: out[b][n][o] = sum_m U[n][m] * ospec[b][m][o]
    kGemm<false, false, MM, 1>
        <<<dim3(NN / 128, 1, BB), 128, SMEM_GC>>>(
            dUr, dos, out, MM, COUT, COUT, (size_t)MM * COUT, (size_t)NN * COUT);
}